// round 3
// baseline (speedup 1.0000x reference)
#include <cuda_runtime.h>
#include <cstdint>

// ----------------------------------------------------------------------------
// HashingDiscretizer — width-robust version.
//
// Logical inputs: input_keys int64[NNZ], input_vals f32[NNZ],
//                 feature_ids int64[F] (sorted, = arange here),
//                 bin_vals f32[F*63] (row-sorted).
// Output: concat(out_keys, out_vals) promoted to f64[2*NNZ]
//         (or f32[2*NNZ] if the harness downcasts 64-bit dtypes).
//
// Harness width scenarios handled:
//   FLAT64: int64 buffers passed natively (counts as documented), out f64.
//   SCEN-C: int64 reinterpreted as int32 with 2x counts (host-detectable:
//           largest size == 2x second-largest); data still int64 bytes; out
//           written as f64 bytes.
//   FLAT32: int64 value-cast to int32 (same counts; device probe on the
//           arange feature_ids distinguishes from FLAT64), out f32.
// ----------------------------------------------------------------------------

static constexpr int  LUT_SIZE = 65536;
static constexpr int  NBIN     = 63;
static constexpr int  ROW      = 72;        // 8 splitters + 8 leaves * 8
static constexpr int  MAX_F    = 8192;
static constexpr unsigned int GOLDEN = 0x9E3779B9u;
static constexpr long long OUT_MASK = 0x3FFFFFLL;   // (1<<22)-1

__device__ int g_is64;                        // 1: 64-bit widths, 0: 32-bit
__device__ unsigned short g_lut[LUT_SIZE];    // idx | (calibrated<<15)
__device__ __align__(32) float g_btree[MAX_F * ROW];

// ---- probe: feature_ids is arange -> word pattern discriminates widths ----
__global__ void probe_kernel(const int* __restrict__ fids_words, int force64) {
    if (threadIdx.x == 0 && blockIdx.x == 0) {
        if (force64) { g_is64 = 1; return; }
        int w1 = fids_words[1];
        int w3 = fids_words[3];
        g_is64 = (w1 == 0 && w3 == 0) ? 1 : 0;  // int64 LE: words (0,0,1,0,...)
    }
}

// ---- K1: key -> (idx, calibrated) LUT over [0, LUT_SIZE) ----
__global__ void build_lut_kernel(const void* __restrict__ fids, int F) {
    int t = blockIdx.x * blockDim.x + threadIdx.x;
    if (t >= LUT_SIZE) return;
    const bool is64 = (g_is64 != 0);
    const long long* f64p = (const long long*)fids;
    const int*       f32p = (const int*)fids;
    long long key = (long long)t;
    int lo = 0, hi = F;
    while (lo < hi) {
        int mid = (lo + hi) >> 1;
        long long fv = is64 ? f64p[mid] : (long long)f32p[mid];
        if (fv < key) lo = mid + 1; else hi = mid;
    }
    int idx = lo < (F - 1) ? lo : (F - 1);
    long long fv = is64 ? f64p[idx] : (long long)f32p[idx];
    unsigned short v = (unsigned short)(idx & 0x7FFF);
    if (fv == key) v |= 0x8000u;
    g_lut[t] = v;
}

// ---- K2: repack 63 boundaries/feature into sector-aligned 8-ary B-tree ----
// row (72 floats, 288 B): [0..7] splitters bins[8j+7] (j<7) + INF pad;
//                         [8+8c+p] leaf c = bins[8c+p] (p<7) + INF pad.
__global__ void build_btree_kernel(const float* __restrict__ bins, int F) {
    int t = blockIdx.x * blockDim.x + threadIdx.x;
    int total = F * ROW;
    if (t >= total) return;
    int f = t / ROW;
    int j = t - f * ROW;
    const float INF = __int_as_float(0x7f800000);
    float v;
    if (j < 8) {
        v = (j < 7) ? __ldg(&bins[f * NBIN + 8 * j + 7]) : INF;
    } else {
        int q = j - 8;
        int l = q >> 3;
        int p = q & 7;
        v = (p < 7) ? __ldg(&bins[f * NBIN + 8 * l + p]) : INF;
    }
    g_btree[t] = v;
}

// ---- per-element transform ----
__device__ __forceinline__ void process_one(long long k, float v,
                                            long long& okey, float& oval,
                                            bool& cal_out) {
    unsigned long long uk = (unsigned long long)k;
    bool cal = false;
    int idx = 0;
    if (uk < (unsigned long long)LUT_SIZE) {
        unsigned short e = g_lut[uk];
        cal = (e & 0x8000u) != 0;
        idx = (int)(e & 0x7FFFu);
    }
    if (cal) {
        const float* nb = g_btree + idx * ROW;
        float4 s0 = *(const float4*)(nb);
        float4 s1 = *(const float4*)(nb + 4);
        int c = (s0.x < v) + (s0.y < v) + (s0.z < v) + (s0.w < v)
              + (s1.x < v) + (s1.y < v) + (s1.z < v) + (s1.w < v);
        const float* lf = nb + 8 + c * 8;
        float4 l0 = *(const float4*)(lf);
        float4 l1 = *(const float4*)(lf + 4);
        int bin = c * 8
              + (l0.x < v) + (l0.y < v) + (l0.z < v) + (l0.w < v)
              + (l1.x < v) + (l1.y < v) + (l1.z < v) + (l1.w < v);
        unsigned int h = ((unsigned int)uk * GOLDEN + (unsigned int)bin) * GOLDEN;
        okey = (long long)(h & (unsigned int)OUT_MASK);
        oval = 1.0f;
    } else {
        okey = (k & OUT_MASK);
        oval = v;
    }
    cal_out = cal;
}

template <bool IS64>
__device__ __forceinline__ void run_range(const void* __restrict__ keysv,
                                          const float* __restrict__ vals,
                                          int nnz, void* __restrict__ outv) {
    int t = blockIdx.x * blockDim.x + threadIdx.x;
    int i0 = t * 2;
    if (i0 >= nnz) return;

    long long k0, k1;
    if (IS64) {
        const long long* keys = (const long long*)keysv;
        if (i0 + 1 < nnz) {
            longlong2 kk = *(const longlong2*)(keys + i0);
            k0 = kk.x; k1 = kk.y;
        } else { k0 = keys[i0]; k1 = 0; }
    } else {
        const int* keys = (const int*)keysv;
        if (i0 + 1 < nnz) {
            int2 kk = *(const int2*)(keys + i0);
            k0 = (long long)kk.x; k1 = (long long)kk.y;
        } else { k0 = (long long)keys[i0]; k1 = 0; }
    }

    if (i0 + 1 < nnz) {
        float2 vv = *(const float2*)(vals + i0);
        long long ok0, ok1; float ov0, ov1; bool c0, c1;
        process_one(k0, vv.x, ok0, ov0, c0);
        process_one(k1, vv.y, ok1, ov1, c1);
        if (IS64) {
            double* out = (double*)outv;
            *(double2*)(out + i0)       = make_double2((double)ok0, (double)ok1);
            *(double2*)(out + nnz + i0) = make_double2((double)ov0, (double)ov1);
        } else {
            float* out = (float*)outv;
            *(float2*)(out + i0)       = make_float2((float)ok0, (float)ok1);
            *(float2*)(out + nnz + i0) = make_float2(ov0, ov1);
        }
    } else {
        long long ok; float ov; bool c;
        process_one(k0, vals[i0], ok, ov, c);
        if (IS64) {
            double* out = (double*)outv;
            out[i0] = (double)ok;
            out[nnz + i0] = (double)ov;
        } else {
            float* out = (float*)outv;
            out[i0] = (float)ok;
            out[nnz + i0] = ov;
        }
    }
}

__global__ void __launch_bounds__(256)
hashing_discretizer_kernel(const void* __restrict__ keys,
                           const float* __restrict__ vals,
                           int nnz, void* __restrict__ out) {
    if (g_is64) run_range<true>(keys, vals, nnz, out);
    else        run_range<false>(keys, vals, nnz, out);
}

extern "C" void kernel_launch(void* const* d_in, const int* in_sizes, int n_in,
                              void* d_out, int out_size) {
    // ---- classify inputs by element count (order-agnostic) ----
    long long s[16];
    int n = n_in < 16 ? n_in : 16;
    for (int i = 0; i < n; i++) s[i] = (long long)in_sizes[i];

    // largest & second largest sizes
    long long m1 = -1, m2 = -1;
    for (int i = 0; i < n; i++) {
        if (s[i] > m1) { m2 = m1; m1 = s[i]; }
        else if (s[i] > m2) { m2 = s[i]; }
    }

    int ik = -1, iv = -1;
    long long nnz_ll;
    int force64 = 0;
    if (m1 == m2) {
        // FLAT: keys & vals both report nnz elements (first occurrence = keys)
        for (int i = 0; i < n; i++)
            if (s[i] == m1) { if (ik < 0) ik = i; else if (iv < 0) iv = i; }
        nnz_ll = m1;
    } else {
        // SCEN-C: int64 reinterpreted as 2x int32 words; keys = max entry,
        // vals = the nnz-sized entry.
        for (int i = 0; i < n; i++) {
            if (s[i] == m1 && ik < 0) ik = i;
            else if (s[i] == m1 / 2 && iv < 0) iv = i;
        }
        nnz_ll = m1 / 2;
        force64 = 1;
    }
    if (iv < 0) iv = ik;

    // remaining two entries: smaller -> feature_ids, larger -> bin_vals
    int ia = -1, ib = -1;
    for (int i = 0; i < n; i++) {
        if (i == ik || i == iv) continue;
        if (ia < 0) ia = i; else if (ib < 0) ib = i;
    }
    if (ib < 0) ib = ia;
    int iF = (s[ia] <= s[ib]) ? ia : ib;
    int iB = (iF == ia) ? ib : ia;

    int nnz = (int)nnz_ll;
    int F = (int)(force64 ? s[iF] / 2 : s[iF]);   // SCEN-C doubles word counts
    if (F > MAX_F) F = MAX_F;
    if (F < 1) F = 1;

    const void*  keys = d_in[ik];
    const float* vals = (const float*)d_in[iv];
    const void*  fids = d_in[iF];
    const float* bins = (const float*)d_in[iB];

    probe_kernel<<<1, 32>>>((const int*)fids, force64);
    build_lut_kernel<<<(LUT_SIZE + 255) / 256, 256>>>(fids, F);
    build_btree_kernel<<<(F * ROW + 255) / 256, 256>>>(bins, F);

    int nthreads = (nnz + 1) / 2;
    hashing_discretizer_kernel<<<(nthreads + 255) / 256, 256>>>(
        keys, vals, nnz, d_out);
}

// round 4
// speedup vs baseline: 1.2127x; 1.2127x over previous
#include <cuda_runtime.h>
#include <cstdint>

// ----------------------------------------------------------------------------
// HashingDiscretizer — R4.
// Hot path verified in R3: harness passes keys as int32 and output as float32
// (concat [keys | vals], 2*nnz elems). 64-bit paths kept as guarded fallbacks.
// New in R4: runtime-verified arange fast path (no LUT gather), streaming
// cache hints, 4 elems/thread, fused setup.
// ----------------------------------------------------------------------------

static constexpr int  LUT_SIZE = 65536;
static constexpr int  NBIN     = 63;
static constexpr int  ROW      = 72;        // 8 splitters + 8 leaves * 8
static constexpr int  MAX_F    = 8192;
static constexpr unsigned GOLDEN = 0x9E3779B9u;
static constexpr unsigned OUT_MASK_U = 0x3FFFFFu;        // (1<<22)-1

__device__ int g_is64;          // 1: int64 inputs / f64 out, 0: int32 / f32
__device__ int g_not_arange;    // 0: feature_ids == arange(F) (fast path ok)
__device__ unsigned short g_lut[LUT_SIZE];               // fallback LUT
__device__ __align__(32) float g_btree[MAX_F * ROW];

// ---- K0 (1 thread): width probe + flag reset -------------------------------
__global__ void init_kernel(const int* __restrict__ fw, int force64) {
    g_is64 = force64 ? 1 : ((fw[1] == 0 && fw[3] == 0) ? 1 : 0);
    g_not_arange = 0;
}

// ---- K1: fused arange-check + LUT build + btree repack ---------------------
// btree row (72 floats, 288B, 32B-aligned):
//   [0..7]   splitters bins[8j+7] (j<7), +INF pad
//   [8+8c+p] leaf c = bins[8c+p] (p<7), +INF pad
__global__ void build_tables(const void* __restrict__ fids,
                             const float* __restrict__ bins,
                             int F, int total_btree) {
    int t = blockIdx.x * blockDim.x + threadIdx.x;
    const bool is64 = (g_is64 != 0);
    const long long* f64p = (const long long*)fids;
    const int*       f32p = (const int*)fids;

    if (t < LUT_SIZE) {
        if (t < F) {
            long long fv = is64 ? f64p[t] : (long long)f32p[t];
            if (fv != (long long)t) atomicOr(&g_not_arange, 1);
        }
        long long key = (long long)t;
        int lo = 0, hi = F;
        while (lo < hi) {
            int mid = (lo + hi) >> 1;
            long long fv = is64 ? f64p[mid] : (long long)f32p[mid];
            if (fv < key) lo = mid + 1; else hi = mid;
        }
        int idx = lo < (F - 1) ? lo : (F - 1);
        long long fv = is64 ? f64p[idx] : (long long)f32p[idx];
        unsigned short v = (unsigned short)(idx & 0x7FFF);
        if (fv == key) v |= 0x8000u;
        g_lut[t] = v;
    }
    if (t < total_btree) {
        int f = t / ROW;
        int j = t - f * ROW;
        const float INF = __int_as_float(0x7f800000);
        float v;
        if (j < 8) {
            v = (j < 7) ? __ldg(&bins[f * NBIN + 8 * j + 7]) : INF;
        } else {
            int q = j - 8, l = q >> 3, p = q & 7;
            v = (p < 7) ? __ldg(&bins[f * NBIN + 8 * l + p]) : INF;
        }
        g_btree[t] = v;
    }
}

// ---- per-element transform -------------------------------------------------
template <bool AR>
__device__ __forceinline__ void process_one(long long k, float v, int F,
                                            unsigned& okey, float& oval) {
    unsigned long long u = (unsigned long long)k;
    bool cal;
    int idx;
    if (AR) {
        cal = u < (unsigned long long)F;
        idx = (int)u;
    } else {
        if (u < (unsigned long long)LUT_SIZE) {
            unsigned short e = g_lut[u];
            cal = (e & 0x8000u) != 0;
            idx = (int)(e & 0x7FFFu);
        } else { cal = false; idx = 0; }
    }
    if (cal) {
        const float* nb = g_btree + idx * ROW;
        float4 s0 = *(const float4*)(nb);
        float4 s1 = *(const float4*)(nb + 4);
        int c = (s0.x < v) + (s0.y < v) + (s0.z < v) + (s0.w < v)
              + (s1.x < v) + (s1.y < v) + (s1.z < v) + (s1.w < v);
        const float* lf = nb + 8 + c * 8;
        float4 l0 = *(const float4*)(lf);
        float4 l1 = *(const float4*)(lf + 4);
        int bin = c * 8
              + (l0.x < v) + (l0.y < v) + (l0.z < v) + (l0.w < v)
              + (l1.x < v) + (l1.y < v) + (l1.z < v) + (l1.w < v);
        unsigned h = ((unsigned)u * GOLDEN + (unsigned)bin) * GOLDEN;
        okey = h & OUT_MASK_U;
        oval = 1.0f;
    } else {
        okey = (unsigned)((unsigned long long)k & OUT_MASK_U);
        oval = v;
    }
}

template <bool IS64, bool AR>
__device__ __forceinline__ void run4(const void* __restrict__ keysv,
                                     const float* __restrict__ vals,
                                     int nnz, void* __restrict__ outv, int F) {
    int t = blockIdx.x * blockDim.x + threadIdx.x;
    int i0 = t * 4;
    if (i0 >= nnz) return;

    if (i0 + 3 < nnz) {
        long long k[4];
        if (IS64) {
            const long long* kp = (const long long*)keysv + i0;
            longlong2 a = __ldcs((const longlong2*)kp);
            longlong2 b = __ldcs((const longlong2*)(kp + 2));
            k[0] = a.x; k[1] = a.y; k[2] = b.x; k[3] = b.y;
        } else {
            int4 a = __ldcs((const int4*)((const int*)keysv + i0));
            k[0] = a.x; k[1] = a.y; k[2] = a.z; k[3] = a.w;
        }
        float4 vv = __ldcs((const float4*)(vals + i0));
        unsigned ok[4]; float ov[4];
        process_one<AR>(k[0], vv.x, F, ok[0], ov[0]);
        process_one<AR>(k[1], vv.y, F, ok[1], ov[1]);
        process_one<AR>(k[2], vv.z, F, ok[2], ov[2]);
        process_one<AR>(k[3], vv.w, F, ok[3], ov[3]);

        if (IS64) {
            double* out = (double*)outv;
            __stcs((double2*)(out + i0),     make_double2((double)ok[0], (double)ok[1]));
            __stcs((double2*)(out + i0 + 2), make_double2((double)ok[2], (double)ok[3]));
            if ((nnz & 1) == 0) {
                __stcs((double2*)(out + nnz + i0),     make_double2((double)ov[0], (double)ov[1]));
                __stcs((double2*)(out + nnz + i0 + 2), make_double2((double)ov[2], (double)ov[3]));
            } else {
                out[nnz+i0] = ov[0]; out[nnz+i0+1] = ov[1];
                out[nnz+i0+2] = ov[2]; out[nnz+i0+3] = ov[3];
            }
        } else {
            float* out = (float*)outv;
            __stcs((float4*)(out + i0),
                   make_float4((float)ok[0], (float)ok[1], (float)ok[2], (float)ok[3]));
            if ((nnz & 3) == 0) {
                __stcs((float4*)(out + nnz + i0),
                       make_float4(ov[0], ov[1], ov[2], ov[3]));
            } else {
                out[nnz+i0] = ov[0]; out[nnz+i0+1] = ov[1];
                out[nnz+i0+2] = ov[2]; out[nnz+i0+3] = ov[3];
            }
        }
    } else {
        for (int i = i0; i < nnz; i++) {
            long long k = IS64 ? ((const long long*)keysv)[i]
                               : (long long)((const int*)keysv)[i];
            unsigned ok; float ov;
            process_one<AR>(k, vals[i], F, ok, ov);
            if (IS64) {
                double* out = (double*)outv;
                out[i] = (double)ok; out[nnz + i] = (double)ov;
            } else {
                float* out = (float*)outv;
                out[i] = (float)ok;  out[nnz + i] = ov;
            }
        }
    }
}

__global__ void __launch_bounds__(256)
hashing_discretizer_kernel(const void* __restrict__ keys,
                           const float* __restrict__ vals,
                           int nnz, void* __restrict__ out, int F) {
    const bool is64 = (g_is64 != 0);
    const bool ar   = (g_not_arange == 0);
    if (is64) { if (ar) run4<true, true >(keys, vals, nnz, out, F);
                else    run4<true, false>(keys, vals, nnz, out, F); }
    else      { if (ar) run4<false, true >(keys, vals, nnz, out, F);
                else    run4<false, false>(keys, vals, nnz, out, F); }
}

extern "C" void kernel_launch(void* const* d_in, const int* in_sizes, int n_in,
                              void* d_out, int out_size) {
    // ---- classify inputs by element count (order-agnostic) ----
    long long s[16];
    int n = n_in < 16 ? n_in : 16;
    for (int i = 0; i < n; i++) s[i] = (long long)in_sizes[i];

    long long m1 = -1, m2 = -1;
    for (int i = 0; i < n; i++) {
        if (s[i] > m1) { m2 = m1; m1 = s[i]; }
        else if (s[i] > m2) { m2 = s[i]; }
    }

    int ik = -1, iv = -1;
    long long nnz_ll;
    int force64 = 0;
    if (m1 == m2) {
        for (int i = 0; i < n; i++)
            if (s[i] == m1) { if (ik < 0) ik = i; else if (iv < 0) iv = i; }
        nnz_ll = m1;
    } else {
        // int64 reinterpreted as 2x int32 words: keys = max, vals = max/2 entry
        for (int i = 0; i < n; i++) {
            if (s[i] == m1 && ik < 0) ik = i;
            else if (s[i] == m1 / 2 && iv < 0) iv = i;
        }
        nnz_ll = m1 / 2;
        force64 = 1;
    }
    if (iv < 0) iv = ik;

    int ia = -1, ib = -1;
    for (int i = 0; i < n; i++) {
        if (i == ik || i == iv) continue;
        if (ia < 0) ia = i; else if (ib < 0) ib = i;
    }
    if (ib < 0) ib = ia;
    int iF = (s[ia] <= s[ib]) ? ia : ib;   // feature_ids (smaller)
    int iB = (iF == ia) ? ib : ia;         // bin_vals

    int nnz = (int)nnz_ll;
    int F = (int)(force64 ? s[iF] / 2 : s[iF]);
    if (F > MAX_F) F = MAX_F;
    if (F < 1) F = 1;

    const void*  keys = d_in[ik];
    const float* vals = (const float*)d_in[iv];
    const void*  fids = d_in[iF];
    const float* bins = (const float*)d_in[iB];

    init_kernel<<<1, 1>>>((const int*)fids, force64);
    int total_btree = F * ROW;
    int build_n = (total_btree > LUT_SIZE) ? total_btree : LUT_SIZE;
    build_tables<<<(build_n + 255) / 256, 256>>>(fids, bins, F, total_btree);

    int nthreads = (nnz + 3) / 4;
    hashing_discretizer_kernel<<<(nthreads + 255) / 256, 256>>>(
        keys, vals, nnz, d_out, F);
}